// round 4
// baseline (speedup 1.0000x reference)
#include <cuda_runtime.h>
#include <stdint.h>

// Problem constants (fixed by the dataset)
#define NLAT_IN  181
#define NLON_IN  360
#define NLAT_OUT 91
#define NLON_OUT 180
#define KS       9
#define B_       4
#define CIN      32
#define COUT     32
#define BC       128
#define CK       288                     // CIN*KS
#define M_PER_B  (NLAT_OUT * NLON_OUT)   // 16380
#define M_TOT    (B_ * M_PER_B)          // 65520

#define MAX_NNZ  (1 << 21)

// slab geometry (float4 units): [par][rr 0..8][colh 0..179][cg 0..3]
#define SROWS    9
#define ROWF4    (NLON_OUT * 4)          // 720 float4 per row per parity
#define HALF4    (SROWS * ROWF4 + 4)     // 6484 (pad 4 => parity halves offset by 4 mod 8)
#define SLAB4    (2 * HALF4)             // 12968 float4 = 207488 bytes

// ---------------- device scratch (no cudaMalloc allowed) ----------------
__device__ float g_xqt[NLAT_IN * NLON_IN * BC];  // 33.4 MB  xq transposed [pix][bc]
__device__ float g_wt[CK * COUT];                // W transposed [ck][o]
__device__ int   g_hk[NLAT_OUT * KS + 1];        // (h,k) segment starts
__device__ int2  g_pack[MAX_NNZ];                // (rr<<9 | lonh<<1 | par, psi_bits)
__device__ float g_y[(size_t)CK * M_TOT];        // 75.5 MB intermediate [ck][m]
__device__ int   g_is64;

// ---------------- 1) dtype detection (parallel) ----------------
__global__ void detect_kernel(const int* __restrict__ pidx, int nnz) {
    __shared__ int s[8];
    int bad = 0;
    for (int i = (nnz | 1) + 2 * (int)threadIdx.x; i < 2 * nnz; i += 512)
        bad |= pidx[i];
    #pragma unroll
    for (int o = 16; o; o >>= 1) bad |= __shfl_xor_sync(~0u, bad, o);
    if ((threadIdx.x & 31) == 0) s[threadIdx.x >> 5] = bad;
    __syncthreads();
    if (threadIdx.x == 0) {
        int b = 0;
        #pragma unroll
        for (int i = 0; i < 8; i++) b |= s[i];
        g_is64 = (b == 0) ? 1 : 0;
    }
}

// ---------------- 2) fused pack + (h,k) boundaries ----------------
__global__ void packhk_kernel(const void* __restrict__ pidx,
                              const float* __restrict__ pvals, int nnz) {
    int e = blockIdx.x * blockDim.x + threadIdx.x;
    if (e >= nnz) return;
    int is64 = g_is64;
    int k, h, flat, kp = -1, hp = -1;
    if (is64) {
        const long long* p = (const long long*)pidx;
        k = (int)p[e]; h = (int)p[(long long)nnz + e]; flat = (int)p[2LL * nnz + e];
        if (e > 0) { kp = (int)p[e - 1]; hp = (int)p[(long long)nnz + e - 1]; }
    } else {
        const int* p = (const int*)pidx;
        k = p[e]; h = p[nnz + e]; flat = p[2 * nnz + e];
        if (e > 0) { kp = p[e - 1]; hp = p[nnz + e - 1]; }
    }
    int row = flat / NLON_IN;
    int lon = flat - row * NLON_IN;
    int row0 = 2 * h - 4; if (row0 < 0) row0 = 0;
    int rr = row - row0;
    rr = rr < 0 ? 0 : (rr > 8 ? 8 : rr);     // memory-safety clamp (data guarantees 0..8)
    int lonh = lon >> 1, par = lon & 1;
    int2 pk;
    pk.x = (rr << 9) | (lonh << 1) | par;
    pk.y = __float_as_int(pvals[e]);
    g_pack[e] = pk;

    int key  = h * KS + k;
    int prev = (e == 0) ? -1 : (hp * KS + kp);
    for (int t = prev + 1; t <= key; t++) g_hk[t] = e;
    if (e == nnz - 1)
        for (int t = key + 1; t <= NLAT_OUT * KS; t++) g_hk[t] = nnz;
}

// ---------------- 3) fused xq-transpose + W-transpose ----------------
__global__ void __launch_bounds__(256) xqwt_kernel(const float* __restrict__ x,
                                                   const float* __restrict__ qw,
                                                   const float* __restrict__ w) {
    int bi = blockIdx.x;
    if (bi < 8688) {
        __shared__ float tile[32][33];
        int g0 = bi % 12, g1 = (bi / 12) % 4, row = bi / 48;
        int lon0 = g0 * 32, bc0 = g1 * 32;
        int tx = threadIdx.x & 31, ty = threadIdx.x >> 5;   // 32 x 8
        float q = qw[row];
        for (int i = ty; i < 32; i += 8) {
            int lon = lon0 + tx;
            float v = 0.f;
            if (lon < NLON_IN)
                v = x[((size_t)(bc0 + i) * NLAT_IN + row) * NLON_IN + lon];
            tile[i][tx] = v * q;
        }
        __syncthreads();
        for (int i = ty; i < 32; i += 8) {
            int lon = lon0 + i;
            if (lon < NLON_IN)
                g_xqt[((size_t)(row * NLON_IN + lon)) * BC + bc0 + tx] = tile[tx][i];
        }
    } else {
        int id = (bi - 8688) * 256 + threadIdx.x;
        if (id < COUT * CK) {
            int o = id / CK;
            int ck = id - o * CK;
            g_wt[ck * COUT + o] = w[id];
        }
    }
}

// ---------------- 4) slab conv: y[ck][m] for one (h, b, chalf) per block ----
__global__ void __launch_bounds__(256) conv_kernel() {
    extern __shared__ float4 slab4[];
    int bid = blockIdx.x;                 // 728 = 91 * 8
    int u  = bid >> 3;
    int h = (u & 1) ? (90 - (u >> 1)) : (u >> 1);   // heavy polar rows first
    int bz = bid & 7;
    int b = bz >> 1, z = bz & 1;
    int t = threadIdx.x;
    int row0 = 2 * h - 4; if (row0 < 0) row0 = 0;
    int boff = b * 32 + z * 16;

    // ---- load slab: rows row0..row0+8, all 360 cols, 16 channels (4 float4) ----
    for (int uu = t; uu < SROWS * NLON_IN * 4; uu += 256) {
        int pix = uu >> 2, q = uu & 3;
        int r = pix / NLON_IN;
        int col = pix - r * NLON_IN;
        int row = row0 + r;
        float4 v = make_float4(0.f, 0.f, 0.f, 0.f);
        if (row < NLAT_IN)
            v = *(const float4*)&g_xqt[((size_t)(row * NLON_IN + col)) * BC + boff + q * 4];
        slab4[(col & 1) * HALF4 + r * ROWF4 + (col >> 1) * 4 + q] = v;
    }
    __syncthreads();

    int warp = t >> 5, lane = t & 31;
    int wl = lane >> 2, cg = lane & 3;    // lane = wl*4 + cg

    // ---- 3 passes of 8 warp-walks; each walk covers 8 longitudes ----
    for (int pass = 0; pass < 3; pass++) {
        int g = pass * 8 + warp;          // 0..23
        int w = g * 8 + wl;               // 0..191
        int weff = (w < NLON_OUT) ? w : 0;

        float y[4][KS];
        #pragma unroll
        for (int ci = 0; ci < 4; ci++)
            #pragma unroll
            for (int k = 0; k < KS; k++) y[ci][k] = 0.f;

        #pragma unroll
        for (int k = 0; k < KS; k++) {
            int e0 = g_hk[h * KS + k];
            int e1 = g_hk[h * KS + k + 1];
            #pragma unroll 2
            for (int e = e0; e < e1; e++) {
                int2 pk = __ldg(&g_pack[e]);
                int rr   = pk.x >> 9;
                int lonh = (pk.x >> 1) & 255;
                int par  = pk.x & 1;
                float pv = __int_as_float(pk.y);
                int s = lonh + weff; if (s >= NLON_OUT) s -= NLON_OUT;
                float4 v = slab4[par * HALF4 + rr * ROWF4 + s * 4 + cg];
                y[0][k] = fmaf(pv, v.x, y[0][k]);
                y[1][k] = fmaf(pv, v.y, y[1][k]);
                y[2][k] = fmaf(pv, v.z, y[2][k]);
                y[3][k] = fmaf(pv, v.w, y[3][k]);
            }
        }

        if (w < NLON_OUT) {
            int m = b * M_PER_B + h * NLON_OUT + w;
            #pragma unroll
            for (int ci = 0; ci < 4; ci++)
                #pragma unroll
                for (int k = 0; k < KS; k++) {
                    int ck = (z * 16 + cg * 4 + ci) * KS + k;
                    g_y[(size_t)ck * M_TOT + m] = y[ci][k];
                }
        }
    }
}

// ---------------- 5) stage-2 GEMM: out = W[32x288] * Y[288xM] + bias ----
__global__ void __launch_bounds__(256) gemm_kernel(const float* __restrict__ bias,
                                                   float* __restrict__ out) {
    __shared__ float s_w[CK * COUT];      // 36 KB
    int t = threadIdx.x;
    for (int i = t; i < CK * COUT; i += 256) s_w[i] = g_wt[i];
    __syncthreads();

    int m = blockIdx.x * 256 + t;
    bool ok = m < M_TOT;
    int mc = ok ? m : 0;

    float acc[32];
    #pragma unroll
    for (int o = 0; o < 32; o++) acc[o] = 0.f;

    #pragma unroll 4
    for (int k = 0; k < CK; k++) {
        float yv = __ldg(&g_y[(size_t)k * M_TOT + mc]);
        #pragma unroll
        for (int o4 = 0; o4 < 8; o4++) {
            float4 wv = *(const float4*)&s_w[k * COUT + o4 * 4];
            acc[o4 * 4 + 0] = fmaf(wv.x, yv, acc[o4 * 4 + 0]);
            acc[o4 * 4 + 1] = fmaf(wv.y, yv, acc[o4 * 4 + 1]);
            acc[o4 * 4 + 2] = fmaf(wv.z, yv, acc[o4 * 4 + 2]);
            acc[o4 * 4 + 3] = fmaf(wv.w, yv, acc[o4 * 4 + 3]);
        }
    }

    if (ok) {
        int b = m / M_PER_B;
        int hw = m - b * M_PER_B;
        float* op = out + ((size_t)b * COUT) * M_PER_B + hw;
        #pragma unroll
        for (int o = 0; o < 32; o++)
            op[(size_t)o * M_PER_B] = acc[o] + __ldg(&bias[o]);
    }
}

// ---------------- launch ----------------
extern "C" void kernel_launch(void* const* d_in, const int* in_sizes, int n_in,
                              void* d_out, int out_size) {
    const float* x      = (const float*)d_in[0];
    const float* qw     = (const float*)d_in[1];
    const float* pvals  = (const float*)d_in[2];
    const float* weight = (const float*)d_in[3];
    const float* bias   = (const float*)d_in[4];
    const void*  pidx   = d_in[5];
    float* out = (float*)d_out;

    int nnz = in_sizes[2];

    cudaFuncSetAttribute(conv_kernel,
                         cudaFuncAttributeMaxDynamicSharedMemorySize,
                         SLAB4 * (int)sizeof(float4));

    detect_kernel<<<1, 256>>>((const int*)pidx, nnz);                  // launch 1
    packhk_kernel<<<(nnz + 255) / 256, 256>>>(pidx, pvals, nnz);       // launch 2
    xqwt_kernel<<<8724, 256>>>(x, qw, weight);                         // launch 3
    conv_kernel<<<NLAT_OUT * 8, 256, SLAB4 * sizeof(float4)>>>();      // launch 4 (profiled)
    gemm_kernel<<<(M_TOT + 255) / 256, 256>>>(bias, out);              // launch 5
}

// round 5
// speedup vs baseline: 1.5788x; 1.5788x over previous
#include <cuda_runtime.h>
#include <stdint.h>

// Problem constants (fixed by the dataset)
#define NLAT_IN  181
#define NLON_IN  360
#define NLAT_OUT 91
#define NLON_OUT 180
#define KS       9
#define B_       4
#define CIN      32
#define COUT     32
#define BC       128
#define CK       288                     // CIN*KS

#define WT       10                      // longitudes per block (10 warps)
#define NWTILES  (NLON_OUT / WT)         // 18

#define MAX_NNZ   (1 << 21)
#define NCELL     (9 * NLON_IN)          // 3240 (rr, lon) cells per output lat
#define MAXPAIR_H 16384

// ---------------- device scratch (no cudaMalloc allowed) ----------------
__device__ float    g_xqt[NLAT_IN * NLON_IN * BC];   // 33.4 MB  xq transposed [pix][bc]
__device__ float    g_wt[CK * COUT];                 // W transposed [ck][o]
__device__ int2     g_ent[MAX_NNZ];                  // decoded entries: (k<<12|cell, psi_bits)
__device__ int      g_he[NLAT_OUT + 1];              // per-h entry ranges
__device__ uint32_t g_hdr[NLAT_OUT * NCELL];         // per-h pixel headers (compact)
__device__ uint32_t g_pairs[NLAT_OUT * MAXPAIR_H];   // psi with k in low 4 mantissa bits
__device__ int      g_npix[NLAT_OUT];

// ---------------- 1) decode entries + per-h ranges ----------------
// dtype: word pidx32[2*nnz-1] is h_last=90 (int32) or high half of flat (=0, int64)
__global__ void decode_kernel(const int* __restrict__ pidx,
                              const float* __restrict__ pvals, int nnz) {
    int e = blockIdx.x * blockDim.x + threadIdx.x;
    if (e >= nnz || e >= MAX_NNZ) return;
    int is64 = (pidx[2 * nnz - 1] == 0) ? 1 : 0;
    int k, h, flat, hp = -1;
    if (is64) {
        const long long* p = (const long long*)pidx;
        k = (int)p[e]; h = (int)p[(long long)nnz + e]; flat = (int)p[2LL * nnz + e];
        if (e > 0) hp = (int)p[(long long)nnz + e - 1];
    } else {
        k = pidx[e]; h = pidx[nnz + e]; flat = pidx[2 * nnz + e];
        if (e > 0) hp = pidx[nnz + e - 1];
    }
    int row = flat / NLON_IN;
    int lon = flat - row * NLON_IN;
    int row0 = 2 * h - 4; if (row0 < 0) row0 = 0;
    int rr = row - row0;
    rr = rr < 0 ? 0 : (rr > 8 ? 8 : rr);             // safety clamp (data guarantees 0..8)
    int2 ent;
    ent.x = (k << 12) | (rr * NLON_IN + lon);
    ent.y = __float_as_int(pvals[e]);
    g_ent[e] = ent;

    for (int t = hp + 1; t <= h; t++) g_he[t] = e;   // h is ascending
    if (e == nnz - 1)
        for (int t = h + 1; t <= NLAT_OUT; t++) g_he[t] = nnz;
}

// ---------------- 2) per-h build: count -> scan -> headers -> scatter ----------------
__global__ void __launch_bounds__(1024) build_kernel() {
    __shared__ int s_cnt[NCELL];                     // 12.96 KB
    __shared__ int s_wf[32], s_wc[32];
    __shared__ int s_pixb, s_pairb;
    int h = blockIdx.x;
    int t = threadIdx.x, lane = t & 31, wid = t >> 5;
    int row0 = 2 * h - 4; if (row0 < 0) row0 = 0;

    for (int c = t; c < NCELL; c += 1024) s_cnt[c] = 0;
    if (t == 0) { s_pixb = 0; s_pairb = 0; }
    __syncthreads();

    int e0 = g_he[h], e1 = g_he[h + 1];
    for (int e = e0 + t; e < e1; e += 1024)
        atomicAdd(&s_cnt[g_ent[e].x & 4095], 1);
    __syncthreads();

    // chunked block scan over 3240 cells: compact headers + pair cursors
    for (int c0 = 0; c0 < NCELL; c0 += 1024) {
        int cell = c0 + t;
        int cnt = (cell < NCELL) ? s_cnt[cell] : 0;
        int flag = (cnt > 0) ? 1 : 0;
        int sf = flag, sc = cnt;
        #pragma unroll
        for (int o = 1; o < 32; o <<= 1) {
            int vf = __shfl_up_sync(~0u, sf, o);
            int vc = __shfl_up_sync(~0u, sc, o);
            if (lane >= o) { sf += vf; sc += vc; }
        }
        if (lane == 31) { s_wf[wid] = sf; s_wc[wid] = sc; }
        __syncthreads();
        if (wid == 0) {
            int wf = s_wf[lane], wc = s_wc[lane];
            #pragma unroll
            for (int o = 1; o < 32; o <<= 1) {
                int vf = __shfl_up_sync(~0u, wf, o);
                int vc = __shfl_up_sync(~0u, wc, o);
                if (lane >= o) { wf += vf; wc += vc; }
            }
            s_wf[lane] = wf; s_wc[lane] = wc;
        }
        __syncthreads();
        int exf = sf - flag + ((wid > 0) ? s_wf[wid - 1] : 0);
        int exc = sc - cnt + ((wid > 0) ? s_wc[wid - 1] : 0);
        int pixb = s_pixb, pairb = s_pairb;
        if (flag) {
            int slot = pixb + exf;
            int po   = pairb + exc;
            if (po + cnt <= MAXPAIR_H) {
                int rr  = cell / NLON_IN;
                int lon = cell - rr * NLON_IN;
                int rowbase = (row0 + rr) * NLON_IN;
                int c15 = cnt < 15 ? cnt : 15;
                g_hdr[h * NCELL + slot] = ((uint32_t)c15 << 26) |
                                          ((uint32_t)rowbase << 9) | (uint32_t)lon;
                s_cnt[cell] = po;                    // repurpose as scatter cursor
            } else {
                s_cnt[cell] = -(1 << 28);            // overflow: drop (never expected)
            }
        }
        __syncthreads();
        if (t == 0) { s_pixb += s_wf[31]; s_pairb += s_wc[31]; }
        __syncthreads();
    }
    if (t == 0) g_npix[h] = s_pixb;
    __syncthreads();

    // scatter psi (with k packed in low 4 mantissa bits) into grouped stream
    for (int e = e0 + t; e < e1; e += 1024) {
        int2 ent = g_ent[e];
        int cell = ent.x & 4095;
        int k    = (ent.x >> 12) & 15;
        int slot = atomicAdd(&s_cnt[cell], 1);
        if (slot >= 0 && slot < MAXPAIR_H)
            g_pairs[h * MAXPAIR_H + slot] = ((uint32_t)ent.y & ~15u) | (uint32_t)k;
    }
}

// ---------------- 3) fused xq-transpose + W-transpose ----------------
__global__ void __launch_bounds__(256) xqwt_kernel(const float* __restrict__ x,
                                                   const float* __restrict__ qw,
                                                   const float* __restrict__ w) {
    int bi = blockIdx.x;
    if (bi < 8688) {
        __shared__ float tile[32][33];
        int g0 = bi % 12, g1 = (bi / 12) % 4, row = bi / 48;
        int lon0 = g0 * 32, bc0 = g1 * 32;
        int tx = threadIdx.x & 31, ty = threadIdx.x >> 5;   // 32 x 8
        float q = qw[row];
        for (int i = ty; i < 32; i += 8) {
            int lon = lon0 + tx;
            float v = 0.f;
            if (lon < NLON_IN)
                v = x[((size_t)(bc0 + i) * NLAT_IN + row) * NLON_IN + lon];
            tile[i][tx] = v * q;
        }
        __syncthreads();
        for (int i = ty; i < 32; i += 8) {
            int lon = lon0 + i;
            if (lon < NLON_IN)
                g_xqt[((size_t)(row * NLON_IN + lon)) * BC + bc0 + tx] = tile[tx][i];
        }
    } else {
        int id = (bi - 8688) * 256 + threadIdx.x;
        if (id < COUT * CK) {
            int o = id / CK;
            int ck = id - o * CK;
            g_wt[ck * COUT + o] = w[id];
        }
    }
}

// ---------------- 4) fused conv: pixel-dedup gather + stage-2 GEMM ----------------
#define FMA4(K) { y[0][K] = fmaf(pv, v.x, y[0][K]); y[1][K] = fmaf(pv, v.y, y[1][K]); \
                  y[2][K] = fmaf(pv, v.z, y[2][K]); y[3][K] = fmaf(pv, v.w, y[3][K]); }

__global__ void __launch_bounds__(WT * 32, 2) conv_kernel(const float* __restrict__ bias,
                                                          float* __restrict__ out) {
    __shared__ float s_acc[WT * 4 * 289];            // 46.2 KB

    int wt = blockIdx.x;
    int u  = blockIdx.y;
    int h  = (u & 1) ? (90 - (u >> 1)) : (u >> 1);   // heavy polar rows first
    int lane = threadIdx.x & 31;
    int warp = threadIdx.x >> 5;
    int w = wt * WT + warp;
    int tw = 2 * w;
    int vbase = lane * 4;

    int np = g_npix[h];
    const uint32_t* __restrict__ hdr = g_hdr + h * NCELL;
    const uint32_t* __restrict__ prs = g_pairs + h * MAXPAIR_H;

    float y[4][KS];
    #pragma unroll
    for (int ci = 0; ci < 4; ci++)
        #pragma unroll
        for (int k = 0; k < KS; k++) y[ci][k] = 0.f;

    // software pipeline: prefetch next header + gather
    uint32_t hd = (np > 0) ? __ldg(&hdr[0]) : 0;
    float4 v = make_float4(0.f, 0.f, 0.f, 0.f);
    if (np > 0) {
        int col = (int)(hd & 511) + tw; if (col >= NLON_IN) col -= NLON_IN;
        int rowbase = (int)((hd >> 9) & 0x1FFFF);
        v = __ldg((const float4*)&g_xqt[((size_t)(rowbase + col)) * BC + vbase]);
    }
    int cur = 0;
    for (int p = 0; p < np; p++) {
        uint32_t hdn = 0;
        float4 vn = make_float4(0.f, 0.f, 0.f, 0.f);
        if (p + 1 < np) {
            hdn = __ldg(&hdr[p + 1]);
            int cn = (int)(hdn & 511) + tw; if (cn >= NLON_IN) cn -= NLON_IN;
            int rbn = (int)((hdn >> 9) & 0x1FFFF);
            vn = __ldg((const float4*)&g_xqt[((size_t)(rbn + cn)) * BC + vbase]);
        }
        int cnt = (int)(hd >> 26);
        #pragma unroll 1
        for (int j = 0; j < cnt; j++) {
            uint32_t pk = __ldg(&prs[cur + j]);
            float pv = __uint_as_float(pk & ~15u);
            switch (pk & 15u) {
                case 0: FMA4(0); break;
                case 1: FMA4(1); break;
                case 2: FMA4(2); break;
                case 3: FMA4(3); break;
                case 4: FMA4(4); break;
                case 5: FMA4(5); break;
                case 6: FMA4(6); break;
                case 7: FMA4(7); break;
                default: FMA4(8); break;
            }
        }
        cur += cnt; hd = hdn; v = vn;
    }

    // stage-1 result -> smem [wslot*4+b][c*9+k]
    int boff = lane >> 3;
    int c0 = (lane & 7) * 4;
    int sb = (warp * 4 + boff) * 289 + c0 * KS;
    #pragma unroll
    for (int ci = 0; ci < 4; ci++)
        #pragma unroll
        for (int k = 0; k < KS; k++)
            s_acc[sb + ci * KS + k] = y[ci][k];
    __syncthreads();

    // stage 2: out[b,o,h,w] = sum_ck W[o][ck] * y[b][ck] ; lane = o
    float r0 = 0.f, r1 = 0.f, r2 = 0.f, r3 = 0.f;
    int slot0 = warp * 4;
    const float* s0 = &s_acc[(slot0 + 0) * 289];
    const float* s1 = &s_acc[(slot0 + 1) * 289];
    const float* s2 = &s_acc[(slot0 + 2) * 289];
    const float* s3 = &s_acc[(slot0 + 3) * 289];
    #pragma unroll 4
    for (int ck = 0; ck < CK; ck++) {
        float wv = g_wt[ck * COUT + lane];
        r0 = fmaf(wv, s0[ck], r0);
        r1 = fmaf(wv, s1[ck], r1);
        r2 = fmaf(wv, s2[ck], r2);
        r3 = fmaf(wv, s3[ck], r3);
    }
    float bo = bias[lane];
    float rr[4] = {r0, r1, r2, r3};
    #pragma unroll
    for (int p = 0; p < 4; p++) {
        int slot = slot0 + p;
        int wp = slot >> 2;
        int bp = slot & 3;
        out[(((size_t)(bp * COUT + lane)) * NLAT_OUT + h) * NLON_OUT + (wt * WT + wp)]
            = rr[p] + bo;
    }
}

// ---------------- launch ----------------
extern "C" void kernel_launch(void* const* d_in, const int* in_sizes, int n_in,
                              void* d_out, int out_size) {
    const float* x      = (const float*)d_in[0];
    const float* qw     = (const float*)d_in[1];
    const float* pvals  = (const float*)d_in[2];
    const float* weight = (const float*)d_in[3];
    const float* bias   = (const float*)d_in[4];
    const int*   pidx   = (const int*)d_in[5];
    float* out = (float*)d_out;

    int nnz = in_sizes[2];

    decode_kernel<<<(nnz + 255) / 256, 256>>>(pidx, pvals, nnz);        // launch 1
    build_kernel<<<NLAT_OUT, 1024>>>();                                 // launch 2
    xqwt_kernel<<<8724, 256>>>(x, qw, weight);                          // launch 3
    conv_kernel<<<dim3(NWTILES, NLAT_OUT), WT * 32>>>(bias, out);       // launch 4 (profiled)
}

// round 7
// speedup vs baseline: 2.3652x; 1.4981x over previous
#include <cuda_runtime.h>
#include <stdint.h>

// Problem constants (fixed by the dataset)
#define NLAT_IN  181
#define NLON_IN  360
#define NLAT_OUT 91
#define NLON_OUT 180
#define KS       9
#define B_       4
#define CIN      32
#define COUT     32
#define BC       128
#define CK       288                     // CIN*KS

#define WT       10                      // longitudes per block (10 warps)
#define NWTILES  (NLON_OUT / WT)         // 18

#define MAX_NNZ   (1 << 21)
#define NCELL     (9 * NLON_IN)          // 3240 (rr, lon) cells per output lat
#define RECF      12                     // floats per psi record (9 + pad)

// ---------------- device scratch (no cudaMalloc allowed) ----------------
__device__ float    g_xqt[NLAT_IN * NLON_IN * BC];   // 33.4 MB  xq transposed [pix][bc]
__device__ float    g_wt[CK * COUT];                 // W transposed [ck][o]
__device__ int2     g_ent[MAX_NNZ];                  // decoded entries: (k<<12|cell, psi_bits)
__device__ int      g_he[NLAT_OUT + 1];              // per-h entry ranges
__device__ uint32_t g_hdr[NLAT_OUT * NCELL];         // per-h pixel headers: rowbase<<9|lon
__device__ float    g_psi[NLAT_OUT * NCELL * RECF];  // dense psi9 records (14.2 MB)
__device__ int      g_npix[NLAT_OUT];

// ---------------- 1) decode entries + per-h ranges ----------------
// dtype: word pidx32[2*nnz-1] is h_last=90 (int32) or high half of flat (=0, int64)
__global__ void decode_kernel(const int* __restrict__ pidx,
                              const float* __restrict__ pvals, int nnz) {
    int e = blockIdx.x * blockDim.x + threadIdx.x;
    if (e >= nnz || e >= MAX_NNZ) return;
    int is64 = (pidx[2 * nnz - 1] == 0) ? 1 : 0;
    int k, h, flat, hp = -1;
    if (is64) {
        const long long* p = (const long long*)pidx;
        k = (int)p[e]; h = (int)p[(long long)nnz + e]; flat = (int)p[2LL * nnz + e];
        if (e > 0) hp = (int)p[(long long)nnz + e - 1];
    } else {
        k = pidx[e]; h = pidx[nnz + e]; flat = pidx[2 * nnz + e];
        if (e > 0) hp = pidx[nnz + e - 1];
    }
    int row = flat / NLON_IN;
    int lon = flat - row * NLON_IN;
    int row0 = 2 * h - 4; if (row0 < 0) row0 = 0;
    int rr = row - row0;
    rr = rr < 0 ? 0 : (rr > 8 ? 8 : rr);             // safety clamp (data guarantees 0..8)
    int2 ent;
    ent.x = ((k & 15) << 12) | (rr * NLON_IN + lon);
    ent.y = __float_as_int(pvals[e]);
    g_ent[e] = ent;

    for (int t = hp + 1; t <= h; t++) g_he[t] = e;   // h is ascending
    if (e == nnz - 1)
        for (int t = h + 1; t <= NLAT_OUT; t++) g_he[t] = nnz;
}

// ---------------- 2) per-h build: count -> scan -> zero -> headers+scatter ----------------
__global__ void __launch_bounds__(1024) build_kernel() {
    __shared__ int s_cnt[NCELL];                     // 12.96 KB (count -> slot map)
    __shared__ int s_wf[32];
    __shared__ int s_pixb;
    int h = blockIdx.x;
    int t = threadIdx.x, lane = t & 31, wid = t >> 5;
    int row0 = 2 * h - 4; if (row0 < 0) row0 = 0;

    for (int c = t; c < NCELL; c += 1024) s_cnt[c] = 0;
    if (t == 0) s_pixb = 0;
    __syncthreads();

    int e0 = g_he[h], e1 = g_he[h + 1];
    for (int e = e0 + t; e < e1; e += 1024)
        atomicAdd(&s_cnt[g_ent[e].x & 4095], 1);
    __syncthreads();

    // chunked block scan over 3240 cells: compact slot ids + headers
    for (int c0 = 0; c0 < NCELL; c0 += 1024) {
        int cell = c0 + t;
        int flag = (cell < NCELL && s_cnt[cell] > 0) ? 1 : 0;
        int sf = flag;
        #pragma unroll
        for (int o = 1; o < 32; o <<= 1) {
            int vf = __shfl_up_sync(~0u, sf, o);
            if (lane >= o) sf += vf;
        }
        if (lane == 31) s_wf[wid] = sf;
        __syncthreads();
        if (wid == 0) {
            int wf = s_wf[lane];
            #pragma unroll
            for (int o = 1; o < 32; o <<= 1) {
                int vf = __shfl_up_sync(~0u, wf, o);
                if (lane >= o) wf += vf;
            }
            s_wf[lane] = wf;
        }
        __syncthreads();
        int exf = sf - flag + ((wid > 0) ? s_wf[wid - 1] : 0);
        int pixb = s_pixb;
        if (flag) {
            int slot = pixb + exf;
            int rr  = cell / NLON_IN;
            int lon = cell - rr * NLON_IN;
            int rowbase = (row0 + rr) * NLON_IN;
            g_hdr[h * NCELL + slot] = ((uint32_t)rowbase << 9) | (uint32_t)lon;
            s_cnt[cell] = slot;                      // repurpose as slot map
        }
        __syncthreads();
        if (t == 0) s_pixb += s_wf[31];
        __syncthreads();
    }
    int np = s_pixb;
    if (t == 0) g_npix[h] = np;

    // zero psi records for used slots
    float* psi = g_psi + (size_t)h * NCELL * RECF;
    for (int i = t; i < np * RECF; i += 1024) psi[i] = 0.f;
    __syncthreads();

    // scatter psi into dense 9-vectors (no atomics: (cell,k) unique)
    for (int e = e0 + t; e < e1; e += 1024) {
        int2 ent = g_ent[e];
        int cell = ent.x & 4095;
        int k    = (ent.x >> 12) & 15;
        int slot = s_cnt[cell];
        psi[slot * RECF + k] = __int_as_float(ent.y);
    }
}

// ---------------- 3) fused xq-transpose + W-transpose ----------------
__global__ void __launch_bounds__(256) xqwt_kernel(const float* __restrict__ x,
                                                   const float* __restrict__ qw,
                                                   const float* __restrict__ w) {
    int bi = blockIdx.x;
    if (bi < 8688) {
        __shared__ float tile[32][33];
        int g0 = bi % 12, g1 = (bi / 12) % 4, row = bi / 48;
        int lon0 = g0 * 32, bc0 = g1 * 32;
        int tx = threadIdx.x & 31, ty = threadIdx.x >> 5;   // 32 x 8
        float q = qw[row];
        for (int i = ty; i < 32; i += 8) {
            int lon = lon0 + tx;
            float v = 0.f;
            if (lon < NLON_IN)
                v = x[((size_t)(bc0 + i) * NLAT_IN + row) * NLON_IN + lon];
            tile[i][tx] = v * q;
        }
        __syncthreads();
        for (int i = ty; i < 32; i += 8) {
            int lon = lon0 + i;
            if (lon < NLON_IN)
                g_xqt[((size_t)(row * NLON_IN + lon)) * BC + bc0 + tx] = tile[tx][i];
        }
    } else {
        int id = (bi - 8688) * 256 + threadIdx.x;
        if (id < COUT * CK) {
            int o = id / CK;
            int ck = id - o * CK;
            g_wt[ck * COUT + o] = w[id];
        }
    }
}

// ---------------- 4) fused conv: branch-free dense-psi gather + stage-2 GEMM ----------------
__global__ void __launch_bounds__(WT * 32) conv_kernel(const float* __restrict__ bias,
                                                       float* __restrict__ out) {
    __shared__ float s_acc[WT * 4 * 289];            // 46.2 KB

    int wt = blockIdx.x;
    int u  = blockIdx.y;
    int h  = (u & 1) ? (90 - (u >> 1)) : (u >> 1);   // heavy polar rows first
    int lane = threadIdx.x & 31;
    int warp = threadIdx.x >> 5;
    int w = wt * WT + warp;
    int tw = 2 * w;
    int vbase = lane * 4;

    int np = g_npix[h];
    const uint32_t* __restrict__ hdr = g_hdr + h * NCELL;
    const float*    __restrict__ psi = g_psi + (size_t)h * NCELL * RECF;

    float y[4][KS];
    #pragma unroll
    for (int ci = 0; ci < 4; ci++)
        #pragma unroll
        for (int k = 0; k < KS; k++) y[ci][k] = 0.f;

    #pragma unroll 2
    for (int p = 0; p < np; p++) {
        uint32_t hd = __ldg(&hdr[p]);
        float4 p0 = __ldg((const float4*)&psi[p * RECF + 0]);   // psi 0..3
        float4 p1 = __ldg((const float4*)&psi[p * RECF + 4]);   // psi 4..7
        float  p8 = __ldg(&psi[p * RECF + 8]);                  // psi 8
        int col = (int)(hd & 511) + tw; if (col >= NLON_IN) col -= NLON_IN;
        int rowbase = (int)(hd >> 9);
        float4 v = __ldg((const float4*)&g_xqt[((size_t)(rowbase + col)) * BC + vbase]);
        float vv[4] = {v.x, v.y, v.z, v.w};
        #pragma unroll
        for (int ci = 0; ci < 4; ci++) {
            y[ci][0] = fmaf(p0.x, vv[ci], y[ci][0]);
            y[ci][1] = fmaf(p0.y, vv[ci], y[ci][1]);
            y[ci][2] = fmaf(p0.z, vv[ci], y[ci][2]);
            y[ci][3] = fmaf(p0.w, vv[ci], y[ci][3]);
            y[ci][4] = fmaf(p1.x, vv[ci], y[ci][4]);
            y[ci][5] = fmaf(p1.y, vv[ci], y[ci][5]);
            y[ci][6] = fmaf(p1.z, vv[ci], y[ci][6]);
            y[ci][7] = fmaf(p1.w, vv[ci], y[ci][7]);
            y[ci][8] = fmaf(p8,   vv[ci], y[ci][8]);
        }
    }

    // stage-1 result -> smem [wslot*4+b][c*9+k]
    int boff = lane >> 3;
    int c0 = (lane & 7) * 4;
    int sb = (warp * 4 + boff) * 289 + c0 * KS;
    #pragma unroll
    for (int ci = 0; ci < 4; ci++)
        #pragma unroll
        for (int k = 0; k < KS; k++)
            s_acc[sb + ci * KS + k] = y[ci][k];
    __syncthreads();

    // stage 2: out[b,o,h,w] = sum_ck W[o][ck] * y[b][ck] ; lane = o
    float r0 = 0.f, r1 = 0.f, r2 = 0.f, r3 = 0.f;
    int slot0 = warp * 4;
    const float* s0 = &s_acc[(slot0 + 0) * 289];
    const float* s1 = &s_acc[(slot0 + 1) * 289];
    const float* s2 = &s_acc[(slot0 + 2) * 289];
    const float* s3 = &s_acc[(slot0 + 3) * 289];
    #pragma unroll 4
    for (int ck = 0; ck < CK; ck++) {
        float wv = g_wt[ck * COUT + lane];
        r0 = fmaf(wv, s0[ck], r0);
        r1 = fmaf(wv, s1[ck], r1);
        r2 = fmaf(wv, s2[ck], r2);
        r3 = fmaf(wv, s3[ck], r3);
    }
    float bo = bias[lane];
    float rr[4] = {r0, r1, r2, r3};
    #pragma unroll
    for (int p = 0; p < 4; p++) {
        int slot = slot0 + p;
        int wp = slot >> 2;
        int bp = slot & 3;
        out[(((size_t)(bp * COUT + lane)) * NLAT_OUT + h) * NLON_OUT + (wt * WT + wp)]
            = rr[p] + bo;
    }
}

// ---------------- launch ----------------
extern "C" void kernel_launch(void* const* d_in, const int* in_sizes, int n_in,
                              void* d_out, int out_size) {
    const float* x      = (const float*)d_in[0];
    const float* qw     = (const float*)d_in[1];
    const float* pvals  = (const float*)d_in[2];
    const float* weight = (const float*)d_in[3];
    const float* bias   = (const float*)d_in[4];
    const int*   pidx   = (const int*)d_in[5];
    float* out = (float*)d_out;

    int nnz = in_sizes[2];

    // allow up to 4 CTAs/SM despite 46 KB static smem per CTA
    cudaFuncSetAttribute(conv_kernel,
                         cudaFuncAttributePreferredSharedMemoryCarveout,
                         cudaSharedmemCarveoutMaxShared);

    decode_kernel<<<(nnz + 255) / 256, 256>>>(pidx, pvals, nnz);        // launch 1
    build_kernel<<<NLAT_OUT, 1024>>>();                                 // launch 2
    xqwt_kernel<<<8724, 256>>>(x, qw, weight);                          // launch 3
    conv_kernel<<<dim3(NWTILES, NLAT_OUT), WT * 32>>>(bias, out);       // launch 4 (profiled)
}